// round 11
// baseline (speedup 1.0000x reference)
#include <cuda_runtime.h>
#include <math.h>

// LogSparseAttention, B=2, L=S=2048, H=8, E=D=64, fp32.
// Row l attends to <=22 keys: band l-10..l plus log taps l-10-2^k (l>=22),
// or full causal 0..l (l<22). One warp per (b,l,h) row.
//
// Score phase: 4 keys per pass, 8 lanes per key. Lane c (0..7) owns dims
// 4c..4c+3 and 4c+32..4c+35, so every LDG.128 covers 4 rows x 128B
// contiguous (16 fully-used sectors) -- same coalescing as the 29us kernel
// but only 3 butterfly levels + 1 scatter per 4 keys (24 shfl vs 60).
// V phase: pair-split (lanes 0-15 even keys, 16-31 odd keys, float4 dims).

#define FULL_MASK 0xffffffffu
#define NPAIR 12   // 24 slots

__global__ __launch_bounds__(256)
void logsparse_attn_kernel(const float* __restrict__ Q,
                           const float* __restrict__ K,
                           const float* __restrict__ V,
                           float* __restrict__ O)
{
    constexpr int H = 8;
    constexpr int L = 2048;
    const float scale = 0.125f;  // 1/sqrt(64)

    const int warp = (blockIdx.x * blockDim.x + threadIdx.x) >> 5;
    const int lane = threadIdx.x & 31;

    const int h = warp % H;
    const int l = (warp / H) % L;
    const int b = warp / (H * L);

    const int rowbase = ((b * L + l) * H + h) << 6;   // *64
    const int cbase   = (b << 20) + (h << 6);         // b*L*H*64 + h*64
    const bool smallrow = (l < 22);

    // ---------------- Score phase: 4 keys / pass, 8 lanes / key ----------
    const int g = lane >> 3;     // key group 0..3
    const int c = lane & 7;      // chunk 0..7

    // q chunks: dims 4c..4c+3 and 4c+32..4c+35, scale folded in
    float4 qa = *(const float4*)(Q + rowbase + (c << 2));
    float4 qb = *(const float4*)(Q + rowbase + (c << 2) + 32);
    qa.x *= scale; qa.y *= scale; qa.z *= scale; qa.w *= scale;
    qb.x *= scale; qb.y *= scale; qb.z *= scale; qb.w *= scale;

    // key element-offsets for my group's slot in each of 6 passes
    int koffS[6];
    #pragma unroll
    for (int i = 0; i < 6; ++i) {
        const int tt = 4 * i + g;
        const int klog = l - 10 - (1 << ((tt - 11) & 31));
        int k  = (tt < 11) ? (l - tt) : klog;
        int kv = (tt < 11) ? 1 : (klog >= 0);
        if (smallrow) { k = tt; kv = (tt <= l); }
        koffS[i] = cbase + ((kv ? k : 0) << 9) + (c << 2);
    }

    float myscore = -INFINITY;
    #pragma unroll
    for (int i = 0; i < 6; ++i) {
        const float4 ka = *(const float4*)(K + koffS[i]);
        const float4 kb = *(const float4*)(K + koffS[i] + 32);
        float pp = qa.x * ka.x;
        pp = fmaf(qa.y, ka.y, pp);
        pp = fmaf(qa.z, ka.z, pp);
        pp = fmaf(qa.w, ka.w, pp);
        pp = fmaf(qb.x, kb.x, pp);
        pp = fmaf(qb.y, kb.y, pp);
        pp = fmaf(qb.z, kb.z, pp);
        pp = fmaf(qb.w, kb.w, pp);
        pp += __shfl_xor_sync(FULL_MASK, pp, 1);
        pp += __shfl_xor_sync(FULL_MASK, pp, 2);
        pp += __shfl_xor_sync(FULL_MASK, pp, 4);
        // slot 4i+g's score is in lanes 8g..8g+7; route slot j -> lane j
        const float sb = __shfl_sync(FULL_MASK, pp, (lane & 3) << 3);
        if ((lane >> 2) == i) myscore = sb;
    }

    // ---------------- Validity of my lane's slot (lane == slot) ----------
    bool v;
    if (smallrow) {
        v = (lane <= l);
    } else {
        const int klog = l - 10 - (1 << ((lane - 11) & 31));
        v = (lane < 11) | ((lane < 22) & (klog >= 0));
    }

    // ---------------- Softmax over slots ----------------
    float s = v ? myscore : -INFINITY;
    float mx = s;
    #pragma unroll
    for (int off = 16; off; off >>= 1)
        mx = fmaxf(mx, __shfl_xor_sync(FULL_MASK, mx, off));
    float pe = v ? __expf(s - mx) : 0.0f;
    float sum = pe;
    #pragma unroll
    for (int off = 16; off; off >>= 1)
        sum += __shfl_xor_sync(FULL_MASK, sum, off);
    const float w = pe / sum;

    // ---------------- V phase: pair-split ----------------
    const int half = lane >> 4;
    const int dimoff = (lane & 15) << 2;
    const int vbase = cbase + dimoff;

    int koffV[NPAIR];
    #pragma unroll
    for (int p = 0; p < NPAIR; ++p) {
        const int tt = 2 * p + half;
        const int klog = l - 10 - (1 << ((tt - 11) & 31));
        int k  = (tt < 11) ? (l - tt) : klog;
        int kv = (tt < 11) ? 1 : (klog >= 0);
        if (smallrow) { k = tt; kv = (tt <= l); }
        koffV[p] = vbase + ((kv ? k : 0) << 9);
    }

    float4 accA = make_float4(0.f, 0.f, 0.f, 0.f);
    float4 accB = make_float4(0.f, 0.f, 0.f, 0.f);
    #pragma unroll
    for (int p = 0; p < NPAIR; ++p) {
        const float wj = __shfl_sync(FULL_MASK, w, 2 * p + half);
        const float4 v4 = *(const float4*)(V + koffV[p]);
        if (p & 1) {
            accB.x = fmaf(wj, v4.x, accB.x);
            accB.y = fmaf(wj, v4.y, accB.y);
            accB.z = fmaf(wj, v4.z, accB.z);
            accB.w = fmaf(wj, v4.w, accB.w);
        } else {
            accA.x = fmaf(wj, v4.x, accA.x);
            accA.y = fmaf(wj, v4.y, accA.y);
            accA.z = fmaf(wj, v4.z, accA.z);
            accA.w = fmaf(wj, v4.w, accA.w);
        }
    }
    float4 acc;
    acc.x = accA.x + accB.x;
    acc.y = accA.y + accB.y;
    acc.z = accA.z + accB.z;
    acc.w = accA.w + accB.w;

    acc.x += __shfl_xor_sync(FULL_MASK, acc.x, 16);
    acc.y += __shfl_xor_sync(FULL_MASK, acc.y, 16);
    acc.z += __shfl_xor_sync(FULL_MASK, acc.z, 16);
    acc.w += __shfl_xor_sync(FULL_MASK, acc.w, 16);

    if (lane < 16)
        *(float4*)(O + rowbase + dimoff) = acc;
}

extern "C" void kernel_launch(void* const* d_in, const int* in_sizes, int n_in,
                              void* d_out, int out_size)
{
    (void)in_sizes; (void)n_in; (void)out_size;
    const float* Q = (const float*)d_in[0];
    const float* K = (const float*)d_in[1];
    const float* V = (const float*)d_in[2];
    float* O = (float*)d_out;

    const int total_warps = 2 * 8 * 2048;     // B*H*L
    const int threads = 256;
    const int blocks = total_warps / (threads / 32);
    logsparse_attn_kernel<<<blocks, threads>>>(Q, K, V, O);
}

// round 12
// speedup vs baseline: 1.0257x; 1.0257x over previous
#include <cuda_runtime.h>
#include <math.h>

// LogSparseAttention, B=2, L=S=2048, H=8, E=D=64, fp32.
// Row l attends to <=22 keys: band l-10..l plus log taps l-10-2^k (l>=22),
// or full causal 0..l (l<22). One warp per (b,l,h) row.
//
// Score phase: 4 keys per pass, 8 lanes per key. Lane c (0..7) owns dims
// 4c..4c+3 and 4c+32..4c+35, so every LDG.128 covers 4 rows x 128B
// contiguous (16 fully-used sectors) -- same coalescing as the 29us kernel
// but only 3 butterfly levels + 1 scatter per 4 keys (24 shfl vs 60).
// V phase: pair-split (lanes 0-15 even keys, 16-31 odd keys, float4 dims).

#define FULL_MASK 0xffffffffu
#define NPAIR 12   // 24 slots

__global__ __launch_bounds__(256)
void logsparse_attn_kernel(const float* __restrict__ Q,
                           const float* __restrict__ K,
                           const float* __restrict__ V,
                           float* __restrict__ O)
{
    constexpr int H = 8;
    constexpr int L = 2048;
    const float scale = 0.125f;  // 1/sqrt(64)

    const int warp = (blockIdx.x * blockDim.x + threadIdx.x) >> 5;
    const int lane = threadIdx.x & 31;

    const int h = warp % H;
    const int l = (warp / H) % L;
    const int b = warp / (H * L);

    const int rowbase = ((b * L + l) * H + h) << 6;   // *64
    const int cbase   = (b << 20) + (h << 6);         // b*L*H*64 + h*64
    const bool smallrow = (l < 22);

    // ---------------- Score phase: 4 keys / pass, 8 lanes / key ----------
    const int g = lane >> 3;     // key group 0..3
    const int c = lane & 7;      // chunk 0..7

    // q chunks: dims 4c..4c+3 and 4c+32..4c+35, scale folded in
    float4 qa = *(const float4*)(Q + rowbase + (c << 2));
    float4 qb = *(const float4*)(Q + rowbase + (c << 2) + 32);
    qa.x *= scale; qa.y *= scale; qa.z *= scale; qa.w *= scale;
    qb.x *= scale; qb.y *= scale; qb.z *= scale; qb.w *= scale;

    // key element-offsets for my group's slot in each of 6 passes
    int koffS[6];
    #pragma unroll
    for (int i = 0; i < 6; ++i) {
        const int tt = 4 * i + g;
        const int klog = l - 10 - (1 << ((tt - 11) & 31));
        int k  = (tt < 11) ? (l - tt) : klog;
        int kv = (tt < 11) ? 1 : (klog >= 0);
        if (smallrow) { k = tt; kv = (tt <= l); }
        koffS[i] = cbase + ((kv ? k : 0) << 9) + (c << 2);
    }

    float myscore = -INFINITY;
    #pragma unroll
    for (int i = 0; i < 6; ++i) {
        const float4 ka = *(const float4*)(K + koffS[i]);
        const float4 kb = *(const float4*)(K + koffS[i] + 32);
        float pp = qa.x * ka.x;
        pp = fmaf(qa.y, ka.y, pp);
        pp = fmaf(qa.z, ka.z, pp);
        pp = fmaf(qa.w, ka.w, pp);
        pp = fmaf(qb.x, kb.x, pp);
        pp = fmaf(qb.y, kb.y, pp);
        pp = fmaf(qb.z, kb.z, pp);
        pp = fmaf(qb.w, kb.w, pp);
        pp += __shfl_xor_sync(FULL_MASK, pp, 1);
        pp += __shfl_xor_sync(FULL_MASK, pp, 2);
        pp += __shfl_xor_sync(FULL_MASK, pp, 4);
        // slot 4i+g's score is in lanes 8g..8g+7; route slot j -> lane j
        const float sb = __shfl_sync(FULL_MASK, pp, (lane & 3) << 3);
        if ((lane >> 2) == i) myscore = sb;
    }

    // ---------------- Validity of my lane's slot (lane == slot) ----------
    bool v;
    if (smallrow) {
        v = (lane <= l);
    } else {
        const int klog = l - 10 - (1 << ((lane - 11) & 31));
        v = (lane < 11) | ((lane < 22) & (klog >= 0));
    }

    // ---------------- Softmax over slots ----------------
    float s = v ? myscore : -INFINITY;
    float mx = s;
    #pragma unroll
    for (int off = 16; off; off >>= 1)
        mx = fmaxf(mx, __shfl_xor_sync(FULL_MASK, mx, off));
    float pe = v ? __expf(s - mx) : 0.0f;
    float sum = pe;
    #pragma unroll
    for (int off = 16; off; off >>= 1)
        sum += __shfl_xor_sync(FULL_MASK, sum, off);
    const float w = pe / sum;

    // ---------------- V phase: pair-split ----------------
    const int half = lane >> 4;
    const int dimoff = (lane & 15) << 2;
    const int vbase = cbase + dimoff;

    int koffV[NPAIR];
    #pragma unroll
    for (int p = 0; p < NPAIR; ++p) {
        const int tt = 2 * p + half;
        const int klog = l - 10 - (1 << ((tt - 11) & 31));
        int k  = (tt < 11) ? (l - tt) : klog;
        int kv = (tt < 11) ? 1 : (klog >= 0);
        if (smallrow) { k = tt; kv = (tt <= l); }
        koffV[p] = vbase + ((kv ? k : 0) << 9);
    }

    float4 accA = make_float4(0.f, 0.f, 0.f, 0.f);
    float4 accB = make_float4(0.f, 0.f, 0.f, 0.f);
    #pragma unroll
    for (int p = 0; p < NPAIR; ++p) {
        const float wj = __shfl_sync(FULL_MASK, w, 2 * p + half);
        const float4 v4 = *(const float4*)(V + koffV[p]);
        if (p & 1) {
            accB.x = fmaf(wj, v4.x, accB.x);
            accB.y = fmaf(wj, v4.y, accB.y);
            accB.z = fmaf(wj, v4.z, accB.z);
            accB.w = fmaf(wj, v4.w, accB.w);
        } else {
            accA.x = fmaf(wj, v4.x, accA.x);
            accA.y = fmaf(wj, v4.y, accA.y);
            accA.z = fmaf(wj, v4.z, accA.z);
            accA.w = fmaf(wj, v4.w, accA.w);
        }
    }
    float4 acc;
    acc.x = accA.x + accB.x;
    acc.y = accA.y + accB.y;
    acc.z = accA.z + accB.z;
    acc.w = accA.w + accB.w;

    acc.x += __shfl_xor_sync(FULL_MASK, acc.x, 16);
    acc.y += __shfl_xor_sync(FULL_MASK, acc.y, 16);
    acc.z += __shfl_xor_sync(FULL_MASK, acc.z, 16);
    acc.w += __shfl_xor_sync(FULL_MASK, acc.w, 16);

    if (lane < 16)
        *(float4*)(O + rowbase + dimoff) = acc;
}

extern "C" void kernel_launch(void* const* d_in, const int* in_sizes, int n_in,
                              void* d_out, int out_size)
{
    (void)in_sizes; (void)n_in; (void)out_size;
    const float* Q = (const float*)d_in[0];
    const float* K = (const float*)d_in[1];
    const float* V = (const float*)d_in[2];
    float* O = (float*)d_out;

    const int total_warps = 2 * 8 * 2048;     // B*H*L
    const int threads = 256;
    const int blocks = total_warps / (threads / 32);
    logsparse_attn_kernel<<<blocks, threads>>>(Q, K, V, O);
}

// round 13
// speedup vs baseline: 1.0812x; 1.0541x over previous
#include <cuda_runtime.h>
#include <math.h>

// LogSparseAttention, B=2, L=S=2048, H=8, E=D=64, fp32.
// Row l attends to <=22 keys: band l-10..l plus log taps l-10-2^k (l>=22),
// or full causal 0..l (l<22). One warp per (b,l,h) row.
//
// Score phase: 4 keys per pass, 8 lanes per key. Lane c (0..7) owns dims
// 4c..4c+3 and 4c+32..4c+35, so every LDG.128 covers 4 rows x 128B
// contiguous (16 fully-used sectors) -- same coalescing as the 29us kernel
// but only 3 butterfly levels + 1 scatter per 4 keys (24 shfl vs 60).
// V phase: pair-split (lanes 0-15 even keys, 16-31 odd keys, float4 dims).

#define FULL_MASK 0xffffffffu
#define NPAIR 12   // 24 slots

__global__ __launch_bounds__(256)
void logsparse_attn_kernel(const float* __restrict__ Q,
                           const float* __restrict__ K,
                           const float* __restrict__ V,
                           float* __restrict__ O)
{
    constexpr int H = 8;
    constexpr int L = 2048;
    const float scale = 0.125f;  // 1/sqrt(64)

    const int warp = (blockIdx.x * blockDim.x + threadIdx.x) >> 5;
    const int lane = threadIdx.x & 31;

    const int h = warp % H;
    const int l = (warp / H) % L;
    const int b = warp / (H * L);

    const int rowbase = ((b * L + l) * H + h) << 6;   // *64
    const int cbase   = (b << 20) + (h << 6);         // b*L*H*64 + h*64
    const bool smallrow = (l < 22);

    // ---------------- Score phase: 4 keys / pass, 8 lanes / key ----------
    const int g = lane >> 3;     // key group 0..3
    const int c = lane & 7;      // chunk 0..7

    // q chunks: dims 4c..4c+3 and 4c+32..4c+35, scale folded in
    float4 qa = *(const float4*)(Q + rowbase + (c << 2));
    float4 qb = *(const float4*)(Q + rowbase + (c << 2) + 32);
    qa.x *= scale; qa.y *= scale; qa.z *= scale; qa.w *= scale;
    qb.x *= scale; qb.y *= scale; qb.z *= scale; qb.w *= scale;

    // key element-offsets for my group's slot in each of 6 passes
    int koffS[6];
    #pragma unroll
    for (int i = 0; i < 6; ++i) {
        const int tt = 4 * i + g;
        const int klog = l - 10 - (1 << ((tt - 11) & 31));
        int k  = (tt < 11) ? (l - tt) : klog;
        int kv = (tt < 11) ? 1 : (klog >= 0);
        if (smallrow) { k = tt; kv = (tt <= l); }
        koffS[i] = cbase + ((kv ? k : 0) << 9) + (c << 2);
    }

    float myscore = -INFINITY;
    #pragma unroll
    for (int i = 0; i < 6; ++i) {
        const float4 ka = *(const float4*)(K + koffS[i]);
        const float4 kb = *(const float4*)(K + koffS[i] + 32);
        float pp = qa.x * ka.x;
        pp = fmaf(qa.y, ka.y, pp);
        pp = fmaf(qa.z, ka.z, pp);
        pp = fmaf(qa.w, ka.w, pp);
        pp = fmaf(qb.x, kb.x, pp);
        pp = fmaf(qb.y, kb.y, pp);
        pp = fmaf(qb.z, kb.z, pp);
        pp = fmaf(qb.w, kb.w, pp);
        pp += __shfl_xor_sync(FULL_MASK, pp, 1);
        pp += __shfl_xor_sync(FULL_MASK, pp, 2);
        pp += __shfl_xor_sync(FULL_MASK, pp, 4);
        // slot 4i+g's score is in lanes 8g..8g+7; route slot j -> lane j
        const float sb = __shfl_sync(FULL_MASK, pp, (lane & 3) << 3);
        if ((lane >> 2) == i) myscore = sb;
    }

    // ---------------- Validity of my lane's slot (lane == slot) ----------
    bool v;
    if (smallrow) {
        v = (lane <= l);
    } else {
        const int klog = l - 10 - (1 << ((lane - 11) & 31));
        v = (lane < 11) | ((lane < 22) & (klog >= 0));
    }

    // ---------------- Softmax over slots ----------------
    float s = v ? myscore : -INFINITY;
    float mx = s;
    #pragma unroll
    for (int off = 16; off; off >>= 1)
        mx = fmaxf(mx, __shfl_xor_sync(FULL_MASK, mx, off));
    float pe = v ? __expf(s - mx) : 0.0f;
    float sum = pe;
    #pragma unroll
    for (int off = 16; off; off >>= 1)
        sum += __shfl_xor_sync(FULL_MASK, sum, off);
    const float w = pe / sum;

    // ---------------- V phase: pair-split ----------------
    const int half = lane >> 4;
    const int dimoff = (lane & 15) << 2;
    const int vbase = cbase + dimoff;

    int koffV[NPAIR];
    #pragma unroll
    for (int p = 0; p < NPAIR; ++p) {
        const int tt = 2 * p + half;
        const int klog = l - 10 - (1 << ((tt - 11) & 31));
        int k  = (tt < 11) ? (l - tt) : klog;
        int kv = (tt < 11) ? 1 : (klog >= 0);
        if (smallrow) { k = tt; kv = (tt <= l); }
        koffV[p] = vbase + ((kv ? k : 0) << 9);
    }

    float4 accA = make_float4(0.f, 0.f, 0.f, 0.f);
    float4 accB = make_float4(0.f, 0.f, 0.f, 0.f);
    #pragma unroll
    for (int p = 0; p < NPAIR; ++p) {
        const float wj = __shfl_sync(FULL_MASK, w, 2 * p + half);
        const float4 v4 = *(const float4*)(V + koffV[p]);
        if (p & 1) {
            accB.x = fmaf(wj, v4.x, accB.x);
            accB.y = fmaf(wj, v4.y, accB.y);
            accB.z = fmaf(wj, v4.z, accB.z);
            accB.w = fmaf(wj, v4.w, accB.w);
        } else {
            accA.x = fmaf(wj, v4.x, accA.x);
            accA.y = fmaf(wj, v4.y, accA.y);
            accA.z = fmaf(wj, v4.z, accA.z);
            accA.w = fmaf(wj, v4.w, accA.w);
        }
    }
    float4 acc;
    acc.x = accA.x + accB.x;
    acc.y = accA.y + accB.y;
    acc.z = accA.z + accB.z;
    acc.w = accA.w + accB.w;

    acc.x += __shfl_xor_sync(FULL_MASK, acc.x, 16);
    acc.y += __shfl_xor_sync(FULL_MASK, acc.y, 16);
    acc.z += __shfl_xor_sync(FULL_MASK, acc.z, 16);
    acc.w += __shfl_xor_sync(FULL_MASK, acc.w, 16);

    if (lane < 16)
        *(float4*)(O + rowbase + dimoff) = acc;
}

extern "C" void kernel_launch(void* const* d_in, const int* in_sizes, int n_in,
                              void* d_out, int out_size)
{
    (void)in_sizes; (void)n_in; (void)out_size;
    const float* Q = (const float*)d_in[0];
    const float* K = (const float*)d_in[1];
    const float* V = (const float*)d_in[2];
    float* O = (float*)d_out;

    const int total_warps = 2 * 8 * 2048;     // B*H*L
    const int threads = 256;
    const int blocks = total_warps / (threads / 32);
    logsparse_attn_kernel<<<blocks, threads>>>(Q, K, V, O);
}